// round 2
// baseline (speedup 1.0000x reference)
#include <cuda_runtime.h>
#include <cuda_bf16.h>

// Analytic reduction of the 4-op "nibble machine" (FFN/attn/FFN/attn with
// baked near-zero weights):
//   t      = x3*(1 - x10) + x[b, tok=3, col=1]
//   rawsum = x4 + x0 * t
//   result = x5 + (k>=3 ? rawsum[b, k-3] : 0)
// all other 61 columns: identity copy.  Pure streaming: 256MB in + 256MB out.

constexpr int NTOK = 8;
constexpr int DIM  = 64;
constexpr int ROW  = NTOK * DIM;           // 512 floats per batch row
constexpr int ROWS_PER_BLOCK = 16;
constexpr int THREADS = 256;
constexpr int TILE = ROWS_PER_BLOCK * ROW; // 8192 floats = 32 KB

__global__ __launch_bounds__(THREADS)
void nibble_kernel(const float* __restrict__ in, float* __restrict__ out)
{
    __shared__ float s[TILE];

    const size_t base = (size_t)blockIdx.x * TILE;

    // ---- coalesced load (float4) ----
    const float4* __restrict__ in4 = reinterpret_cast<const float4*>(in + base);
    float4* s4 = reinterpret_cast<float4*>(s);
#pragma unroll
    for (int i = threadIdx.x; i < TILE / 4; i += THREADS)
        s4[i] = in4[i];
    __syncthreads();

    // ---- per-token patch (128 tokens, threads 0..127) ----
    float t = 0.f, rsum = 0.f, res = 0.f;
    const bool active = threadIdx.x < ROWS_PER_BLOCK * NTOK;
    if (active) {
        const int r = threadIdx.x >> 3;   // batch row within tile
        const int k = threadIdx.x & 7;    // token index
        const float* rowp = s + r * ROW;
        const float* tok  = rowp + k * DIM;

        const float b_bc = rowp[3 * DIM + 1];          // x[b, tok 3, NIB_B]

        t    = fmaf(tok[3], 1.0f - tok[10], b_bc);     // TEMP
        rsum = fmaf(tok[0], t, tok[4]);                // RAW_SUM
        res  = tok[5];                                 // RESULT
        if (k >= 3) {
            const float* p = rowp + (k - 3) * DIM;
            const float tp = fmaf(p[3], 1.0f - p[10], b_bc);
            res += fmaf(p[0], tp, p[4]);               // rawsum of token k-3
        }
    }
    __syncthreads();   // all reads done before anyone writes

    if (active) {
        const int r = threadIdx.x >> 3;
        const int k = threadIdx.x & 7;
        float* tok = s + r * ROW + k * DIM;
        tok[3] = t;
        tok[4] = rsum;
        tok[5] = res;
    }
    __syncthreads();

    // ---- coalesced store (float4) ----
    float4* __restrict__ out4 = reinterpret_cast<float4*>(out + base);
#pragma unroll
    for (int i = threadIdx.x; i < TILE / 4; i += THREADS)
        out4[i] = s4[i];
}

extern "C" void kernel_launch(void* const* d_in, const int* in_sizes, int n_in,
                              void* d_out, int out_size)
{
    const float* x = (const float*)d_in[0];
    float* out = (float*)d_out;

    int total = in_sizes[0];                  // BATCH * 8 * 64
    if (total <= 0) total = out_size;
    const int blocks = total / TILE;          // 131072*512/8192 = 8192
    nibble_kernel<<<blocks, THREADS>>>(x, out);
}

// round 3
// speedup vs baseline: 1.1937x; 1.1937x over previous
#include <cuda_runtime.h>
#include <cuda_bf16.h>

// Analytic reduction of the 4-op "nibble machine":
//   t      = x3*(1 - x10) + x[b, tok=3, col=1]
//   rawsum = x4 + x0 * t
//   result = x5 + (k>=3 ? rawsum[b, k-3] : 0)
// all other 61 columns: identity copy.
//
// Pure streaming kernel: one thread = one float4 (16 float4 per 64-float
// token). Only float4 #0 (holds col 3) and #1 (holds cols 4,5) of each token
// get patched; those threads gather the few needed scalars with direct
// global loads (the sectors are in flight from the bulk stream anyway, so
// they hit L1/L2). No shared memory, no barriers.

constexpr int THREADS = 256;

__global__ __launch_bounds__(THREADS)
void nibble_stream_kernel(const float* __restrict__ in, float* __restrict__ out)
{
    const size_t i = (size_t)blockIdx.x * THREADS + threadIdx.x;  // float4 index

    float4 v = reinterpret_cast<const float4*>(in)[i];

    const unsigned c4 = (unsigned)(i & 15);   // float4 index within token

    if (c4 <= 1) {
        const size_t tb = (i & ~(size_t)15) * 4;    // token base (float index)
        const size_t rb = (i & ~(size_t)127) * 4;   // row base   (float index)
        const float b_bc = __ldg(in + rb + 3 * 64 + 1);   // x[b, tok3, col1]

        if (c4 == 0) {
            // v = cols {0,1,2,3}; patch col 3 (TEMP)
            const float x10 = __ldg(in + tb + 10);
            v.w = fmaf(v.w, 1.0f - x10, b_bc);
        } else {
            // v = cols {4,5,6,7}; patch col 4 (RAW_SUM), col 5 (RESULT)
            const float x0  = __ldg(in + tb + 0);
            const float x3  = __ldg(in + tb + 3);
            const float x10 = __ldg(in + tb + 10);
            const float t   = fmaf(x3, 1.0f - x10, b_bc);
            v.x = fmaf(x0, t, v.x);                       // rawsum

            const int k = (int)((i >> 4) & 7);            // token index
            if (k >= 3) {
                const float* p = in + tb - 3 * 64;        // predecessor token
                const float tp = fmaf(__ldg(p + 3), 1.0f - __ldg(p + 10), b_bc);
                v.y += fmaf(__ldg(p + 0), tp, __ldg(p + 4));  // + rawsum[k-3]
            }
        }
    }

    reinterpret_cast<float4*>(out)[i] = v;
}

extern "C" void kernel_launch(void* const* d_in, const int* in_sizes, int n_in,
                              void* d_out, int out_size)
{
    const float* x = (const float*)d_in[0];
    float* out = (float*)d_out;

    int total = in_sizes[0];                  // BATCH * 8 * 64 floats
    if (total <= 0) total = out_size;
    const int total4 = total / 4;             // float4 count
    const int blocks = (total4 + THREADS - 1) / THREADS;   // 65536
    nibble_stream_kernel<<<blocks, THREADS>>>(x, out);
}

// round 5
// speedup vs baseline: 1.2238x; 1.0252x over previous
#include <cuda_runtime.h>
#include <cuda_bf16.h>

// Analytic reduction of the 4-op "nibble machine":
//   t      = x3*(1 - x10) + x[b, tok=3, col=1]
//   rawsum = x4 + x0 * t
//   result = x5 + (k>=3 ? rawsum[b, k-3] : 0)
// all other 61 columns: identity copy.
//
// Streaming: each thread owns 4 float4s at stride 256 (block-strided), so all
// four share the same in-token position (256 % 16 == 0) -> the patch branch
// is uniform per thread and evaluated once. 14/16 threads are pure
// LDG.128x4 -> STG.128x4 copies with MLP=4.

constexpr int THREADS = 256;
constexpr int VEC = 4;                       // float4s per thread
constexpr int BLK4 = THREADS * VEC;          // float4s per block

__global__ __launch_bounds__(THREADS)
void nibble_stream4_kernel(const float* __restrict__ in, float* __restrict__ out)
{
    const size_t i0 = (size_t)blockIdx.x * BLK4 + threadIdx.x;  // float4 index

    const float4* __restrict__ in4 = reinterpret_cast<const float4*>(in);
    float4* __restrict__ out4 = reinterpret_cast<float4*>(out);

    float4 v[VEC];
#pragma unroll
    for (int j = 0; j < VEC; j++)
        v[j] = in4[i0 + (size_t)j * THREADS];

    const unsigned c4 = (unsigned)(i0 & 15);  // same for all VEC elements

    if (c4 <= 1) {
#pragma unroll
        for (int j = 0; j < VEC; j++) {
            const size_t i  = i0 + (size_t)j * THREADS;
            const size_t tb = (i & ~(size_t)15) * 4;    // token base (floats)
            const size_t rb = (i & ~(size_t)127) * 4;   // row base   (floats)
            const float b_bc = __ldg(in + rb + 3 * 64 + 1);  // x[b,tok3,col1]

            if (c4 == 0) {
                // v = cols {0,1,2,3}; patch col 3 (TEMP)
                const float x10 = __ldg(in + tb + 10);
                v[j].w = fmaf(v[j].w, 1.0f - x10, b_bc);
            } else {
                // v = cols {4,5,6,7}; patch col 4 (RAW_SUM), col 5 (RESULT)
                const float x0  = __ldg(in + tb + 0);
                const float x3  = __ldg(in + tb + 3);
                const float x10 = __ldg(in + tb + 10);
                const float t   = fmaf(x3, 1.0f - x10, b_bc);
                v[j].x = fmaf(x0, t, v[j].x);                 // rawsum

                const int k = (int)((i >> 4) & 7);            // token index
                if (k >= 3) {
                    const float* p = in + tb - 3 * 64;        // token k-3
                    const float tp = fmaf(__ldg(p + 3), 1.0f - __ldg(p + 10), b_bc);
                    v[j].y += fmaf(__ldg(p + 0), tp, __ldg(p + 4)); // + rawsum[k-3]
                }
            }
        }
    }

#pragma unroll
    for (int j = 0; j < VEC; j++)
        __stcs(out4 + i0 + (size_t)j * THREADS, v[j]);
}

extern "C" void kernel_launch(void* const* d_in, const int* in_sizes, int n_in,
                              void* d_out, int out_size)
{
    const float* x = (const float*)d_in[0];
    float* out = (float*)d_out;

    int total = in_sizes[0];                 // BATCH * 8 * 64 floats
    if (total <= 0) total = out_size;
    const int total4 = total / 4;            // float4 count (16,777,216)
    const int blocks = total4 / BLK4;        // 16384
    nibble_stream4_kernel<<<blocks, THREADS>>>(x, out);
}